// round 11
// baseline (speedup 1.0000x reference)
#include <cuda_runtime.h>

// Problem constants (from reference)
#define VOCAB      30000
#define N_PRE      20000
#define VEC_DIM    300
#define INPUT_SIZE 10000   // VOCAB - N_PRE
#define HIDDEN     256
#define OUT_DIM    556     // VEC_DIM + HIDDEN
#define N_TOKENS   4096    // 8 * 512
#define VEC4       (VEC_DIM / 4)   // 75 float4 per vector row

// Scratch: transposed weight matrix Wt[c][h], c in [0,10000), h in [0,256).
// 10000*256*4 B = 10.24 MB static device global (allowed scratch).
__device__ float g_Wt[(size_t)INPUT_SIZE * HIDDEN];

// ---------------------------------------------------------------------------
// Kernel 1: tiled transpose W[256,10000] -> Wt[10000,256].
// 32x32 tiles, coalesced on both read (along c) and write (along h).
// Grid: (ceil(10000/32)=313, 256/32=8), block (32,8).
// ---------------------------------------------------------------------------
__global__ __launch_bounds__(256)
void transpose_kernel(const float* __restrict__ W)
{
    __shared__ float tile[32][33];

    const int c0 = blockIdx.x * 32;
    const int h0 = blockIdx.y * 32;
    const int tx = threadIdx.x;      // 0..31
    const int ty = threadIdx.y;      // 0..7

#pragma unroll
    for (int i = 0; i < 32; i += 8) {
        const int c = c0 + tx;
        const int h = h0 + ty + i;   // always < 256
        if (c < INPUT_SIZE)
            tile[ty + i][tx] = W[(size_t)h * INPUT_SIZE + c];
    }
    __syncthreads();
#pragma unroll
    for (int i = 0; i < 32; i += 8) {
        const int c = c0 + ty + i;
        const int h = h0 + tx;
        if (c < INPUT_SIZE)
            g_Wt[(size_t)c * HIDDEN + h] = tile[tx][ty + i];
    }
}

// ---------------------------------------------------------------------------
// Kernel 2: main encoder. One warp per token; everything coalesced.
//   hidden: out[tok][300+h] = b[h] + (t>=N_PRE ? Wt[(t-N_PRE)*256 + h] : 0)
//           -> 2 float4 per lane from contiguous Wt column.
//   vector: out[tok][0:300] = t<N_PRE ? vectors[t] : 0  (75 float4 / warp)
// out row base = tok*2224 B (16B aligned); +300 floats = +1200 B (16B aligned).
// ---------------------------------------------------------------------------
__global__ __launch_bounds__(256)
void encoder_main(const int* __restrict__ batch,
                  const float* __restrict__ vectors,
                  const float* __restrict__ b,
                  float* __restrict__ out)
{
    const int warp = threadIdx.x >> 5;
    const int lane = threadIdx.x & 31;
    const int tok  = blockIdx.x * 8 + warp;
    const int t    = batch[tok];     // same addr across warp -> broadcast

    float* __restrict__ out_row = out + (size_t)tok * OUT_DIM;

    // ---- hidden part (coalesced) ----
    const float4* __restrict__ b4 = reinterpret_cast<const float4*>(b);
    float4* __restrict__ oh = reinterpret_cast<float4*>(out_row + VEC_DIM);

    if (t >= N_PRE) {
        const float4* __restrict__ w4 =
            reinterpret_cast<const float4*>(g_Wt + (size_t)(t - N_PRE) * HIDDEN);
#pragma unroll
        for (int k = 0; k < 2; k++) {
            const int idx = lane + 32 * k;
            float4 bb = b4[idx];
            float4 ww = w4[idx];
            oh[idx] = make_float4(bb.x + ww.x, bb.y + ww.y,
                                  bb.z + ww.z, bb.w + ww.w);
        }
    } else {
#pragma unroll
        for (int k = 0; k < 2; k++) {
            const int idx = lane + 32 * k;
            oh[idx] = b4[idx];
        }
    }

    // ---- vector part (coalesced) ----
    float4* __restrict__ ov = reinterpret_cast<float4*>(out_row);
    if (t < N_PRE) {
        const float4* __restrict__ vr =
            reinterpret_cast<const float4*>(vectors + (size_t)t * VEC_DIM);
#pragma unroll 3
        for (int k = lane; k < VEC4; k += 32)
            ov[k] = vr[k];
    } else {
        const float4 z = make_float4(0.f, 0.f, 0.f, 0.f);
#pragma unroll 3
        for (int k = lane; k < VEC4; k += 32)
            ov[k] = z;
    }
}

extern "C" void kernel_launch(void* const* d_in, const int* in_sizes, int n_in,
                              void* d_out, int out_size)
{
    const int*   batch   = (const int*)  d_in[0];
    const float* vectors = (const float*)d_in[1];
    const float* W       = (const float*)d_in[2];
    const float* b       = (const float*)d_in[3];
    float*       out     = (float*)d_out;

    dim3 tgrid((INPUT_SIZE + 31) / 32, HIDDEN / 32);
    dim3 tblk(32, 8);
    transpose_kernel<<<tgrid, tblk>>>(W);

    encoder_main<<<N_TOKENS / 8, 256>>>(batch, vectors, b, out);
}

// round 12
// speedup vs baseline: 1.2547x; 1.2547x over previous
#include <cuda_runtime.h>

// Problem constants (from reference)
#define VOCAB      30000
#define N_PRE      20000
#define VEC_DIM    300
#define INPUT_SIZE 10000   // VOCAB - N_PRE
#define HIDDEN     256
#define OUT_DIM    556     // VEC_DIM + HIDDEN
#define N_TOKENS   4096    // 8 * 512
#define VEC4       (VEC_DIM / 4)   // 75 float4 per vector row

#define TPB_TOK    8       // tokens per block (hidden kernel)

// ---------------------------------------------------------------------------
// Hidden kernel: out[tok][300+h] = b[h] + (t>=N_PRE ? W[h*10000 + (t-N_PRE)] : 0)
// 512 blocks x 256 threads; thread tid = h; 8 tokens/block, MLP=8 on gathers.
// Gather is inherently 32-way line-divergent (h-stride = 40 KB) -> L1tex
// wavefront bound; stores are coalesced 128B/warp.
// ---------------------------------------------------------------------------
__global__ __launch_bounds__(256)
void hidden_kernel(const int* __restrict__ batch,
                   const float* __restrict__ W,
                   const float* __restrict__ b,
                   float* __restrict__ out)
{
    __shared__ int s_idx[TPB_TOK];

    const int tid  = threadIdx.x;
    const int tok0 = blockIdx.x * TPB_TOK;

    if (tid < TPB_TOK)
        s_idx[tid] = batch[tok0 + tid];

    const float bias = b[tid];
    __syncthreads();

    int ts[TPB_TOK];
#pragma unroll
    for (int j = 0; j < TPB_TOK; j++)
        ts[j] = s_idx[j];

    float w[TPB_TOK];
#pragma unroll
    for (int j = 0; j < TPB_TOK; j++) {
        const int t = ts[j];
        w[j] = (t >= N_PRE) ? W[(size_t)tid * INPUT_SIZE + (t - N_PRE)] : 0.f;
    }
#pragma unroll
    for (int j = 0; j < TPB_TOK; j++)
        out[(size_t)(tok0 + j) * OUT_DIM + VEC_DIM + tid] = bias + w[j];
}

// ---------------------------------------------------------------------------
// Vector kernel: out[tok][0:300] = t<N_PRE ? vectors[t] : 0
// One warp per token; 75 float4 per row, fully coalesced both sides.
// 512 blocks x 256 threads (8 warps = 8 tokens per block).
// ---------------------------------------------------------------------------
__global__ __launch_bounds__(256)
void vector_kernel(const int* __restrict__ batch,
                   const float* __restrict__ vectors,
                   float* __restrict__ out)
{
    const int warp = threadIdx.x >> 5;
    const int lane = threadIdx.x & 31;
    const int tok  = blockIdx.x * 8 + warp;
    const int t    = batch[tok];          // warp-uniform -> broadcast

    float4* __restrict__ ov = reinterpret_cast<float4*>(out + (size_t)tok * OUT_DIM);

    if (t < N_PRE) {
        const float4* __restrict__ vr =
            reinterpret_cast<const float4*>(vectors + (size_t)t * VEC_DIM);
#pragma unroll 3
        for (int k = lane; k < VEC4; k += 32)
            ov[k] = vr[k];
    } else {
        const float4 z = make_float4(0.f, 0.f, 0.f, 0.f);
#pragma unroll 3
        for (int k = lane; k < VEC4; k += 32)
            ov[k] = z;
    }
}

extern "C" void kernel_launch(void* const* d_in, const int* in_sizes, int n_in,
                              void* d_out, int out_size)
{
    const int*   batch   = (const int*)  d_in[0];
    const float* vectors = (const float*)d_in[1];
    const float* W       = (const float*)d_in[2];
    const float* b       = (const float*)d_in[3];
    float*       out     = (float*)d_out;

    // Fork a side stream so the two kernels become PARALLEL graph nodes.
    // Host-side stream/event create+destroy only (no device memory); all
    // consumed within this call, so capture sees a clean fork/join diamond.
    cudaStream_t s2;
    cudaStreamCreateWithFlags(&s2, cudaStreamNonBlocking);
    cudaEvent_t eFork, eJoin;
    cudaEventCreateWithFlags(&eFork, cudaEventDisableTiming);
    cudaEventCreateWithFlags(&eJoin, cudaEventDisableTiming);

    cudaEventRecord(eFork, 0);            // on the (captured) null stream
    cudaStreamWaitEvent(s2, eFork, 0);

    hidden_kernel<<<N_TOKENS / TPB_TOK, 256, 0, 0>>>(batch, W, b, out);
    vector_kernel<<<N_TOKENS / 8,       256, 0, s2>>>(batch, vectors, out);

    cudaEventRecord(eJoin, s2);
    cudaStreamWaitEvent(0, eJoin, 0);     // join back into the captured stream

    cudaEventDestroy(eFork);
    cudaEventDestroy(eJoin);
    cudaStreamDestroy(s2);
}